// round 7
// baseline (speedup 1.0000x reference)
#include <cuda_runtime.h>
#include <cuda_fp16.h>
#include <cstdint>

#define D 128
#define EPSV 1e-5f

// ---------------- smem layout (byte offsets into dynamic smem) ----------------
#define AS       264            // fp16 elems per A row (256 cols + 8 pad)
#define A_H      0u             // 128 x 264 fp16 = 67584 B
#define A_L      67584u         // lo tile, same layout
#define WBUF     135168u        // 2 bufs x (hi 10240 + lo 10240)
#define WSTRIDE  40             // fp16 per W row (32 k + 8 pad)
#define WBUFSZ   20480u
#define SM_BIAS  176128u
#define SM_G     176640u
#define SM_BE    177152u
#define SM_SRC   177664u
#define SM_DST   178176u
#define SM_PART  178688u        // 128 rows x 4 colgroups x float2 = 4096 B
#define SMEM_DYN 182784u
// fp32 stage (128 x 132) aliases the A region (only used after all MMAs of a kernel)
#define STG_STRIDE 132

// ---------------- scratch (alloc-free) ----------------
__device__ float g_agg[80000 * D];
__device__ float g_h1[80000 * D];
// prepped weights: per level 524288 B; chunk = 16KB ([n=128][k=32] fp16 hi 8KB + lo 8KB)
__device__ __align__(16) unsigned char g_Wprep[2 * 524288];
#define OFF_BW1 0u
#define OFF_BW2 131072u
#define OFF_SW1 196608u
#define OFF_SW2 327680u
#define OFF_HW  393216u
#define WLEVEL  524288u

// ---------------- PTX helpers (base ISA: valid on compute_103) ----------------
__device__ __forceinline__ uint32_t smem_u32(const void* p) {
    uint32_t a;
    asm("{ .reg .u64 t; cvta.to.shared.u64 t, %1; cvt.u32.u64 %0, t; }" : "=r"(a) : "l"(p));
    return a;
}
#define LDSM4(r, addr) \
    asm volatile("ldmatrix.sync.aligned.m8n8.x4.shared.b16 {%0,%1,%2,%3}, [%4];" \
                 : "=r"((r)[0]), "=r"((r)[1]), "=r"((r)[2]), "=r"((r)[3]) : "r"(addr))
#define MMA16816(dd, a, b0, b1) \
    asm volatile("mma.sync.aligned.m16n8k16.row.col.f32.f16.f16.f32 " \
                 "{%0,%1,%2,%3},{%4,%5,%6,%7},{%8,%9},{%0,%1,%2,%3};" \
                 : "+f"((dd)[0]), "+f"((dd)[1]), "+f"((dd)[2]), "+f"((dd)[3]) \
                 : "r"((a)[0]), "r"((a)[1]), "r"((a)[2]), "r"((a)[3]), "r"(b0), "r"(b1))

// ---------------- fp16 hi/lo split ----------------
__device__ __forceinline__ void split2(float a, float b, uint32_t& hi, uint32_t& lo) {
    __half2 h = __floats2half2_rn(a, b);
    hi = *reinterpret_cast<uint32_t*>(&h);
    __half2 l = __floats2half2_rn(a - __low2float(h), b - __high2float(h));
    lo = *reinterpret_cast<uint32_t*>(&l);
}

// ---------------- gather: 128 fp32 cols -> A hi/lo fp16 tiles at col0 (512 thr) ----------------
__device__ __forceinline__ void gather128(unsigned char* sm, const float4* __restrict__ src,
                                          const int* idx, long long row0, int col0,
                                          int nvalid, int t) {
    int r = t >> 2, q = t & 3;
    int cbase = col0 + q * 32;
    bool ok = r < nvalid;
    long long sr = idx ? (ok ? (long long)idx[r] : 0) : (row0 + r);
    const float4* p = src + sr * 32 + q * 8;
#pragma unroll
    for (int j = 0; j < 8; j++) {
        float4 v = ok ? __ldg(p + j) : make_float4(0.f, 0.f, 0.f, 0.f);
        uint32_t h0, l0, h1, l1;
        split2(v.x, v.y, h0, l0);
        split2(v.z, v.w, h1, l1);
        uint32_t off = (uint32_t)(r * AS + cbase + j * 4) * 2u;
        *(uint2*)(sm + A_H + off) = make_uint2(h0, h1);
        *(uint2*)(sm + A_L + off) = make_uint2(l0, l1);
    }
}

// ---------------- one GEMM layer: K = NC*32, A cols start at kbase ----------------
// 16 warps as 4x4 grid: warp tile = 32 rows x 32 cols. d[32] accumulators.
// Term-major MMA issue (hh, hl, lh): dependent-MMA gap = 8.
__device__ __forceinline__ void run_layer(unsigned char* sm, uint32_t smb,
                                          const unsigned char* __restrict__ w,
                                          int NC, int kbase, float* d,
                                          int t, int lane, int warp) {
#pragma unroll
    for (int i = 0; i < 32; i++) d[i] = 0.f;

    int n = t >> 2, s4 = t & 3;
    int gi = n * 4 + s4;                 // int4 index within 8KB hi image
    int4 vh, vl;
    {   // preload chunk 0 -> buf0
        const int4* g = (const int4*)w;
        vh = __ldg(g + gi); vl = __ldg(g + 512 + gi);
        unsigned char* dh = sm + WBUF + (uint32_t)(n * 80 + s4 * 16);
        *(int4*)dh = vh;
        *(int4*)(dh + 10240) = vl;
    }
    int wrow = (warp & 3) * 32, wcol = (warp >> 2) * 32;
    const uint32_t aconst = smb + A_H +
        (uint32_t)((wrow + (lane & 7) + ((lane >> 3) & 1) * 8) * AS + (lane >> 4) * 8) * 2u;
    const uint32_t bconst = (uint32_t)(((wcol + (lane >> 4) * 8 + (lane & 7)) * WSTRIDE +
                                        ((lane >> 3) & 1) * 8) * 2);

#pragma unroll 1
    for (int c = 0; c < NC; c++) {
        __syncthreads();
        bool more = (c + 1) < NC;
        if (more) {
            const int4* g = (const int4*)(w + (size_t)(c + 1) * 16384u);
            vh = __ldg(g + gi); vl = __ldg(g + 512 + gi);
        }
        uint32_t wbase = smb + WBUF + (uint32_t)(c & 1) * WBUFSZ + bconst;
#pragma unroll
        for (int ks = 0; ks < 2; ks++) {
            uint32_t ah[2][4], al[2][4], bh[2][4], bl[2][4];
            uint32_t aaddr = aconst + (uint32_t)(kbase + c * 32 + ks * 16) * 2u;
            LDSM4(ah[0], aaddr);
            LDSM4(ah[1], aaddr + 16u * AS * 2u);
            uint32_t baddr = wbase + (uint32_t)(ks * 16) * 2u;
            LDSM4(bh[0], baddr);
            LDSM4(bh[1], baddr + 16u * WSTRIDE * 2u);
            LDSM4(al[0], aaddr + A_L);
            LDSM4(al[1], aaddr + A_L + 16u * AS * 2u);
            LDSM4(bl[0], baddr + 10240u);
            LDSM4(bl[1], baddr + 10240u + 16u * WSTRIDE * 2u);

            // term hh
#pragma unroll
            for (int rt = 0; rt < 2; rt++)
#pragma unroll
                for (int nt = 0; nt < 4; nt++)
                    MMA16816(d + (rt * 4 + nt) * 4, ah[rt], bh[nt >> 1][(nt & 1) * 2], bh[nt >> 1][(nt & 1) * 2 + 1]);
            // term hl
#pragma unroll
            for (int rt = 0; rt < 2; rt++)
#pragma unroll
                for (int nt = 0; nt < 4; nt++)
                    MMA16816(d + (rt * 4 + nt) * 4, ah[rt], bl[nt >> 1][(nt & 1) * 2], bl[nt >> 1][(nt & 1) * 2 + 1]);
            // term lh
#pragma unroll
            for (int rt = 0; rt < 2; rt++)
#pragma unroll
                for (int nt = 0; nt < 4; nt++)
                    MMA16816(d + (rt * 4 + nt) * 4, al[rt], bh[nt >> 1][(nt & 1) * 2], bh[nt >> 1][(nt & 1) * 2 + 1]);
        }
        if (more) {
            unsigned char* dh = sm + WBUF + (uint32_t)((c + 1) & 1) * WBUFSZ +
                                (uint32_t)(n * 80 + s4 * 16);
            *(int4*)dh = vh;
            *(int4*)(dh + 10240) = vl;
        }
    }
}

// ---------------- epilogue: bias + LN + ReLU (cross-warp LN via smem partials) ----------------
// mode 0: write fp16 hi/lo back into A tiles at column dstcol. mode 1: fp32 stage.
__device__ __forceinline__ void epilogue(unsigned char* sm, float* d,
                                         const float* __restrict__ b,
                                         const float* __restrict__ g,
                                         const float* __restrict__ be,
                                         int mode, int dstcol, int t, int lane, int warp) {
    float* bs  = (float*)(sm + SM_BIAS);
    float* gs  = (float*)(sm + SM_G);
    float* bes = (float*)(sm + SM_BE);
    float2* part = (float2*)(sm + SM_PART);
    if (t < 128) { bs[t] = b[t]; gs[t] = g[t]; bes[t] = be[t]; }
    __syncthreads();

    int wrow = (warp & 3) * 32, wcol = (warp >> 2) * 32, cg = warp >> 2;
    int rbase = wrow + (lane >> 2);

    float s[4] = {0.f, 0.f, 0.f, 0.f}, q[4] = {0.f, 0.f, 0.f, 0.f};
#pragma unroll
    for (int rt = 0; rt < 2; rt++)
#pragma unroll
        for (int nt = 0; nt < 4; nt++) {
            int di = (rt * 4 + nt) * 4;
            int c0 = wcol + nt * 8 + (lane & 3) * 2;
            float x0 = d[di + 0] + bs[c0];
            float x1 = d[di + 1] + bs[c0 + 1];
            float x2 = d[di + 2] + bs[c0];
            float x3 = d[di + 3] + bs[c0 + 1];
            d[di + 0] = x0; d[di + 1] = x1; d[di + 2] = x2; d[di + 3] = x3;
            s[rt * 2]     += x0 + x1; q[rt * 2]     += x0 * x0 + x1 * x1;
            s[rt * 2 + 1] += x2 + x3; q[rt * 2 + 1] += x2 * x2 + x3 * x3;
        }
#pragma unroll
    for (int j = 0; j < 4; j++) {
        s[j] += __shfl_xor_sync(0xffffffffu, s[j], 1); s[j] += __shfl_xor_sync(0xffffffffu, s[j], 2);
        q[j] += __shfl_xor_sync(0xffffffffu, q[j], 1); q[j] += __shfl_xor_sync(0xffffffffu, q[j], 2);
    }
    if ((lane & 3) == 0) {
#pragma unroll
        for (int j = 0; j < 4; j++) {
            int row = rbase + (j & 1) * 8 + (j >> 1) * 16;
            part[row * 4 + cg] = make_float2(s[j], q[j]);
        }
    }
    __syncthreads();

    float m[4], rv[4];
#pragma unroll
    for (int j = 0; j < 4; j++) {
        int row = rbase + (j & 1) * 8 + (j >> 1) * 16;
        float2 p0 = part[row * 4 + 0], p1 = part[row * 4 + 1];
        float2 p2 = part[row * 4 + 2], p3 = part[row * 4 + 3];
        float sum = p0.x + p1.x + p2.x + p3.x;
        float qq  = p0.y + p1.y + p2.y + p3.y;
        m[j]  = sum * (1.f / 128.f);
        rv[j] = rsqrtf(qq * (1.f / 128.f) - m[j] * m[j] + EPSV);
    }

    float* stg = (float*)sm;
#pragma unroll
    for (int rt = 0; rt < 2; rt++)
#pragma unroll
        for (int nt = 0; nt < 4; nt++) {
            int di = (rt * 4 + nt) * 4;
            int c0 = wcol + nt * 8 + (lane & 3) * 2;
            int j0 = rt * 2, j1 = rt * 2 + 1;
            float y0 = fmaxf(fmaf((d[di + 0] - m[j0]) * rv[j0], gs[c0],     bes[c0]),     0.f);
            float y1 = fmaxf(fmaf((d[di + 1] - m[j0]) * rv[j0], gs[c0 + 1], bes[c0 + 1]), 0.f);
            float y2 = fmaxf(fmaf((d[di + 2] - m[j1]) * rv[j1], gs[c0],     bes[c0]),     0.f);
            float y3 = fmaxf(fmaf((d[di + 3] - m[j1]) * rv[j1], gs[c0 + 1], bes[c0 + 1]), 0.f);
            int r0 = rbase + (j0 & 1) * 8 + rt * 16;   // = rbase + rt*16
            int r1 = r0 + 8;
            if (mode == 0) {
                uint32_t h, l;
                uint32_t o0 = (uint32_t)(r0 * AS + dstcol + c0) * 2u;
                split2(y0, y1, h, l);
                *(uint32_t*)(sm + A_H + o0) = h;
                *(uint32_t*)(sm + A_L + o0) = l;
                uint32_t o1 = (uint32_t)(r1 * AS + dstcol + c0) * 2u;
                split2(y2, y3, h, l);
                *(uint32_t*)(sm + A_H + o1) = h;
                *(uint32_t*)(sm + A_L + o1) = l;
            } else {
                *(float2*)(stg + r0 * STG_STRIDE + c0) = make_float2(y0, y1);
                *(float2*)(stg + r1 * STG_STRIDE + c0) = make_float2(y2, y3);
            }
        }
}

// ---------------- edge kernel ----------------
__global__ __launch_bounds__(512, 1)
void edge_kernel(const float* __restrict__ h, const float* __restrict__ bond,
                 const int* __restrict__ src, const int* __restrict__ dst,
                 const unsigned char* __restrict__ wlev,
                 const float* __restrict__ b1, const float* __restrict__ g1, const float* __restrict__ be1,
                 const float* __restrict__ b2, const float* __restrict__ g2, const float* __restrict__ be2,
                 float* __restrict__ agg, int E) {
    extern __shared__ __align__(16) unsigned char sm[];
    uint32_t smb = smem_u32(sm);
    int t = threadIdx.x, lane = t & 31, warp = t >> 5;
    long long e0 = (long long)blockIdx.x * 128;
    int nvalid = (int)min(128ll, (long long)E - e0);

    int* ssm = (int*)(sm + SM_SRC);
    int* dsm = (int*)(sm + SM_DST);
    if (t < 128) {
        ssm[t] = (t < nvalid) ? src[e0 + t] : 0;
        dsm[t] = (t < nvalid) ? dst[e0 + t] : 0;
    }
    __syncthreads();

    gather128(sm, (const float4*)h, ssm, 0, 0, nvalid, t);
    gather128(sm, (const float4*)bond, nullptr, e0, 128, nvalid, t);

    float d[32];
    run_layer(sm, smb, wlev + OFF_BW1, 8, 0, d, t, lane, warp);
    epilogue(sm, d, b1, g1, be1, 0, 0, t, lane, warp);
    run_layer(sm, smb, wlev + OFF_BW2, 4, 0, d, t, lane, warp);
    epilogue(sm, d, b2, g2, be2, 1, 0, t, lane, warp);
    __syncthreads();

    const float* stg = (const float*)sm;
    int col = t & 127;
    for (int r = t >> 7; r < nvalid; r += 4)
        atomicAdd(&agg[(size_t)dsm[r] * 128 + col], stg[r * STG_STRIDE + col]);
}

// ---------------- node kernel ----------------
__global__ __launch_bounds__(512, 1)
void node_kernel(const float* __restrict__ ax, const float* __restrict__ aggin,
                 const unsigned char* __restrict__ wlev,
                 const float* __restrict__ sb1, const float* __restrict__ sg1, const float* __restrict__ sbe1,
                 const float* __restrict__ sb2, const float* __restrict__ sg2, const float* __restrict__ sbe2,
                 const float* __restrict__ hb, const float* __restrict__ hg, const float* __restrict__ hbe,
                 float* __restrict__ out, int N) {
    extern __shared__ __align__(16) unsigned char sm[];
    uint32_t smb = smem_u32(sm);
    int t = threadIdx.x, lane = t & 31, warp = t >> 5;
    long long n0 = (long long)blockIdx.x * 128;
    int nvalid = (int)min(128ll, (long long)N - n0);

    gather128(sm, (const float4*)ax, nullptr, n0, 0, nvalid, t);
    gather128(sm, (const float4*)aggin, nullptr, n0, 128, nvalid, t);

    float d[32];
    run_layer(sm, smb, wlev + OFF_SW1, 8, 0, d, t, lane, warp);
    epilogue(sm, d, sb1, sg1, sbe1, 0, 128, t, lane, warp);   // f1 -> cols 128..255 (keep ax)
    run_layer(sm, smb, wlev + OFF_SW2, 4, 128, d, t, lane, warp);
    epilogue(sm, d, sb2, sg2, sbe2, 0, 128, t, lane, warp);   // f2 -> cols 128..255
    run_layer(sm, smb, wlev + OFF_HW, 8, 0, d, t, lane, warp);
    epilogue(sm, d, hb, hg, hbe, 1, 0, t, lane, warp);
    __syncthreads();

    const float* stg = (const float*)sm;
    int col = t & 127;
    for (int r = t >> 7; r < nvalid; r += 4)
        out[(n0 + r) * 128 + col] = stg[r * STG_STRIDE + col];
}

// ---------------- weight prep: fp32 W[K][128] -> chunked W^T fp16 hi/lo ----------------
__global__ void prep_kernel(const float* __restrict__ bW1, const float* __restrict__ bW2,
                            const float* __restrict__ sW1, const float* __restrict__ sW2,
                            const float* __restrict__ hW) {
    int level = blockIdx.y, cid = blockIdx.x, t = threadIdx.x;
    const float* W; int c; uint32_t off; int K;
    if (cid < 8)       { W = bW1; c = cid;      off = OFF_BW1; K = 256; }
    else if (cid < 12) { W = bW2; c = cid - 8;  off = OFF_BW2; K = 128; }
    else if (cid < 20) { W = sW1; c = cid - 12; off = OFF_SW1; K = 256; }
    else if (cid < 24) { W = sW2; c = cid - 20; off = OFF_SW2; K = 128; }
    else               { W = hW;  c = cid - 24; off = OFF_HW;  K = 256; }

    const float* wsrc = W + (size_t)level * K * 128 + (size_t)c * 32 * 128;
    unsigned char* dstb = g_Wprep + (size_t)level * WLEVEL + off + (size_t)c * 16384u;
    for (int kk = 0; kk < 32; kk++) {
        float x = wsrc[kk * 128 + t];            // W[k][n], n = t
        __half hi = __float2half_rn(x);
        __half lo = __float2half_rn(x - __half2float(hi));
        uint32_t o = (uint32_t)(t * 32 + kk) * 2u;   // [n][k]
        *(__half*)(dstb + o)         = hi;
        *(__half*)(dstb + 8192u + o) = lo;
    }
}

// ---------------- kernel_launch ----------------
extern "C" void kernel_launch(void* const* d_in, const int* in_sizes, int n_in,
                              void* d_out, int out_size) {
    const float* subtree_h_top = (const float*)d_in[0];
    const float* atom_x_1      = (const float*)d_in[1];
    const float* atom_x_0      = (const float*)d_in[2];
    const float* bond_x_2      = (const float*)d_in[3];
    const float* bond_x_1      = (const float*)d_in[4];
    const float* branch_W1     = (const float*)d_in[5];
    const float* branch_b1     = (const float*)d_in[6];
    const float* branch_g1     = (const float*)d_in[7];
    const float* branch_beta1  = (const float*)d_in[8];
    const float* branch_W2     = (const float*)d_in[9];
    const float* branch_b2     = (const float*)d_in[10];
    const float* branch_g2     = (const float*)d_in[11];
    const float* branch_beta2  = (const float*)d_in[12];
    const float* sub_W1        = (const float*)d_in[13];
    const float* sub_b1        = (const float*)d_in[14];
    const float* sub_g1        = (const float*)d_in[15];
    const float* sub_beta1     = (const float*)d_in[16];
    const float* sub_W2        = (const float*)d_in[17];
    const float* sub_b2        = (const float*)d_in[18];
    const float* sub_g2        = (const float*)d_in[19];
    const float* sub_beta2     = (const float*)d_in[20];
    const float* head_W        = (const float*)d_in[21];
    const float* head_b        = (const float*)d_in[22];
    const float* head_g        = (const float*)d_in[23];
    const float* head_beta     = (const float*)d_in[24];
    const int*   src_2         = (const int*)d_in[25];
    const int*   dst_2         = (const int*)d_in[26];
    const int*   src_1         = (const int*)d_in[27];
    const int*   dst_1         = (const int*)d_in[28];

    const int n2 = in_sizes[0] / D;
    const int n1 = in_sizes[1] / D;
    const int n0 = in_sizes[2] / D;

    float* agg; cudaGetSymbolAddress((void**)&agg, g_agg);
    float* h1;  cudaGetSymbolAddress((void**)&h1,  g_h1);
    unsigned char* wprep; cudaGetSymbolAddress((void**)&wprep, g_Wprep);
    float* out = (float*)d_out;

    static bool attr_done = false;
    if (!attr_done) {
        cudaFuncSetAttribute(edge_kernel, cudaFuncAttributeMaxDynamicSharedMemorySize, SMEM_DYN);
        cudaFuncSetAttribute(node_kernel, cudaFuncAttributeMaxDynamicSharedMemorySize, SMEM_DYN);
        attr_done = true;
    }

    const int V = D;

    prep_kernel<<<dim3(32, 2), 128>>>(branch_W1, branch_W2, sub_W1, sub_W2, head_W);

    // level 0: n2 edges -> n1 nodes
    cudaMemsetAsync(agg, 0, (size_t)n1 * D * sizeof(float));
    edge_kernel<<<(n2 + 127) / 128, 512, SMEM_DYN>>>(
        subtree_h_top, bond_x_2, src_2, dst_2, wprep,
        branch_b1, branch_g1, branch_beta1,
        branch_b2, branch_g2, branch_beta2, agg, n2);
    node_kernel<<<(n1 + 127) / 128, 512, SMEM_DYN>>>(
        atom_x_1, agg, wprep,
        sub_b1, sub_g1, sub_beta1,
        sub_b2, sub_g2, sub_beta2,
        head_b, head_g, head_beta, h1, n1);

    // level 1: n1 edges -> n0 nodes
    cudaMemsetAsync(agg, 0, (size_t)n0 * D * sizeof(float));
    edge_kernel<<<(n1 + 127) / 128, 512, SMEM_DYN>>>(
        h1, bond_x_1, src_1, dst_1, wprep + WLEVEL,
        branch_b1 + V, branch_g1 + V, branch_beta1 + V,
        branch_b2 + V, branch_g2 + V, branch_beta2 + V, agg, n1);
    node_kernel<<<(n0 + 127) / 128, 512, SMEM_DYN>>>(
        atom_x_0, agg, wprep + WLEVEL,
        sub_b1 + V, sub_g1 + V, sub_beta1 + V,
        sub_b2 + V, sub_g2 + V, sub_beta2 + V,
        head_b + V, head_g + V, head_beta + V, out, n0);
}

// round 8
// speedup vs baseline: 1.0618x; 1.0618x over previous
#include <cuda_runtime.h>
#include <cuda_fp16.h>
#include <cstdint>

#define D 128
#define EPSV 1e-5f
#define ROWS 64

// ---------------- smem layout (byte offsets into dynamic smem) ----------------
#define AS       264            // fp16 elems per A row (256 cols + 8 pad)
#define A_H      0u             // 64 x 264 fp16 = 33792 B
#define A_L      33792u
#define WBUF     67584u         // single buffer: hi 10240 + lo 10240
#define WSTRIDE  40             // fp16 per W row (32 k + 8 pad)
#define SM_BIAS  88064u
#define SM_G     88576u
#define SM_BE    89088u
#define SM_SRC   89600u
#define SM_DST   89856u
#define SM_PART  90112u         // 64 rows x 4 colgroups x float2 = 2048 B
#define SMEM_DYN 92160u
// fp32 stage (64 x 132 = 33792B) aliases A_H (used only after all MMAs)
#define STG_STRIDE 132

// ---------------- scratch (alloc-free) ----------------
__device__ float g_agg[80000 * D];
__device__ float g_h1[80000 * D];
// prepped weights: per level 524288 B; chunk = 16KB ([n=128][k=32] fp16 hi 8KB + lo 8KB)
__device__ __align__(16) unsigned char g_Wprep[2 * 524288];
#define OFF_BW1 0u
#define OFF_BW2 131072u
#define OFF_SW1 196608u
#define OFF_SW2 327680u
#define OFF_HW  393216u
#define WLEVEL  524288u

// ---------------- PTX helpers (base ISA: valid on compute_103) ----------------
__device__ __forceinline__ uint32_t smem_u32(const void* p) {
    uint32_t a;
    asm("{ .reg .u64 t; cvta.to.shared.u64 t, %1; cvt.u32.u64 %0, t; }" : "=r"(a) : "l"(p));
    return a;
}
#define LDSM4(r, addr) \
    asm volatile("ldmatrix.sync.aligned.m8n8.x4.shared.b16 {%0,%1,%2,%3}, [%4];" \
                 : "=r"((r)[0]), "=r"((r)[1]), "=r"((r)[2]), "=r"((r)[3]) : "r"(addr))
#define MMA16816(dd, a, b0, b1) \
    asm volatile("mma.sync.aligned.m16n8k16.row.col.f32.f16.f16.f32 " \
                 "{%0,%1,%2,%3},{%4,%5,%6,%7},{%8,%9},{%0,%1,%2,%3};" \
                 : "+f"((dd)[0]), "+f"((dd)[1]), "+f"((dd)[2]), "+f"((dd)[3]) \
                 : "r"((a)[0]), "r"((a)[1]), "r"((a)[2]), "r"((a)[3]), "r"(b0), "r"(b1))

// ---------------- fp16 hi/lo split ----------------
__device__ __forceinline__ void split2(float a, float b, uint32_t& hi, uint32_t& lo) {
    __half2 h = __floats2half2_rn(a, b);
    hi = *reinterpret_cast<uint32_t*>(&h);
    __half2 l = __floats2half2_rn(a - __low2float(h), b - __high2float(h));
    lo = *reinterpret_cast<uint32_t*>(&l);
}

// ---------------- gather: 64 rows x 128 fp32 cols -> A hi/lo fp16 tiles at col0 ----------------
__device__ __forceinline__ void gather64(unsigned char* sm, const float4* __restrict__ src,
                                         const int* idx, long long row0, int col0,
                                         int nvalid, int t) {
    int r = t >> 2, q = t & 3;
    int cbase = col0 + q * 32;
    bool ok = r < nvalid;
    long long sr = idx ? (ok ? (long long)idx[r] : 0) : (row0 + r);
    const float4* p = src + sr * 32 + q * 8;
#pragma unroll
    for (int j = 0; j < 8; j++) {
        float4 v = ok ? __ldg(p + j) : make_float4(0.f, 0.f, 0.f, 0.f);
        uint32_t h0, l0, h1, l1;
        split2(v.x, v.y, h0, l0);
        split2(v.z, v.w, h1, l1);
        uint32_t off = (uint32_t)(r * AS + cbase + j * 4) * 2u;
        *(uint2*)(sm + A_H + off) = make_uint2(h0, h1);
        *(uint2*)(sm + A_L + off) = make_uint2(l0, l1);
    }
}

// ---------------- W chunk load helpers (256 threads, 16KB chunk) ----------------
__device__ __forceinline__ void wload(const unsigned char* __restrict__ w, int c, int t,
                                      int4& vh0, int4& vh1, int4& vl0, int4& vl1) {
    const int4* g = (const int4*)(w + (size_t)c * 16384u);
    int gi = (t >> 1) * 4 + (t & 1) * 2;
    vh0 = __ldg(g + gi); vh1 = __ldg(g + gi + 1);
    vl0 = __ldg(g + 512 + gi); vl1 = __ldg(g + 512 + gi + 1);
}
__device__ __forceinline__ void wstore(unsigned char* sm, int t,
                                       const int4& vh0, const int4& vh1,
                                       const int4& vl0, const int4& vl1) {
    unsigned char* dh = sm + WBUF + (uint32_t)((t >> 1) * 80 + (t & 1) * 32);
    *(int4*)dh = vh0; *(int4*)(dh + 16) = vh1;
    *(int4*)(dh + 10240) = vl0; *(int4*)(dh + 10240 + 16) = vl1;
}

// ---------------- one GEMM layer: K = NC*32, A cols start at kbase ----------------
// 8 warps as 2row x 4col grid: warp tile = 32 rows x 32 cols. d[32] accumulators.
__device__ __forceinline__ void run_layer(unsigned char* sm, uint32_t smb,
                                          const unsigned char* __restrict__ w,
                                          int NC, int kbase, float* d,
                                          int t, int lane, int warp) {
#pragma unroll
    for (int i = 0; i < 32; i++) d[i] = 0.f;

    int4 vh0, vh1, vl0, vl1;
    wload(w, 0, t, vh0, vh1, vl0, vl1);

    int wrow = (warp & 1) * 32, wcol = (warp >> 1) * 32;
    const uint32_t aconst = smb + A_H +
        (uint32_t)((wrow + (lane & 7) + ((lane >> 3) & 1) * 8) * AS + (lane >> 4) * 8) * 2u;
    const uint32_t bconst = smb + WBUF +
        (uint32_t)(((wcol + (lane >> 4) * 8 + (lane & 7)) * WSTRIDE + ((lane >> 3) & 1) * 8) * 2);

#pragma unroll 1
    for (int c = 0; c < NC; c++) {
        __syncthreads();            // consumers of previous chunk done; WBUF free
        wstore(sm, t, vh0, vh1, vl0, vl1);
        if (c + 1 < NC) wload(w, c + 1, t, vh0, vh1, vl0, vl1);
        __syncthreads();            // WBUF ready
#pragma unroll
        for (int ks = 0; ks < 2; ks++) {
            uint32_t ah[2][4], al[2][4], bh[2][4], bl[2][4];
            uint32_t aaddr = aconst + (uint32_t)(kbase + c * 32 + ks * 16) * 2u;
            LDSM4(ah[0], aaddr);
            LDSM4(ah[1], aaddr + 16u * AS * 2u);
            uint32_t baddr = bconst + (uint32_t)(ks * 16) * 2u;
            LDSM4(bh[0], baddr);
            LDSM4(bh[1], baddr + 16u * WSTRIDE * 2u);
            LDSM4(al[0], aaddr + A_L);
            LDSM4(al[1], aaddr + A_L + 16u * AS * 2u);
            LDSM4(bl[0], baddr + 10240u);
            LDSM4(bl[1], baddr + 10240u + 16u * WSTRIDE * 2u);

            // term hh
#pragma unroll
            for (int rt = 0; rt < 2; rt++)
#pragma unroll
                for (int nt = 0; nt < 4; nt++)
                    MMA16816(d + (rt * 4 + nt) * 4, ah[rt], bh[nt >> 1][(nt & 1) * 2], bh[nt >> 1][(nt & 1) * 2 + 1]);
            // term hl
#pragma unroll
            for (int rt = 0; rt < 2; rt++)
#pragma unroll
                for (int nt = 0; nt < 4; nt++)
                    MMA16816(d + (rt * 4 + nt) * 4, ah[rt], bl[nt >> 1][(nt & 1) * 2], bl[nt >> 1][(nt & 1) * 2 + 1]);
            // term lh
#pragma unroll
            for (int rt = 0; rt < 2; rt++)
#pragma unroll
                for (int nt = 0; nt < 4; nt++)
                    MMA16816(d + (rt * 4 + nt) * 4, al[rt], bh[nt >> 1][(nt & 1) * 2], bh[nt >> 1][(nt & 1) * 2 + 1]);
        }
    }
}

// ---------------- epilogue: bias + LN + ReLU (cross-warp LN via smem partials) ----------------
// mode 0: write fp16 hi/lo back into A tiles at column dstcol. mode 1: fp32 stage.
__device__ __forceinline__ void epilogue(unsigned char* sm, float* d,
                                         const float* __restrict__ b,
                                         const float* __restrict__ g,
                                         const float* __restrict__ be,
                                         int mode, int dstcol, int t, int lane, int warp) {
    float* bs  = (float*)(sm + SM_BIAS);
    float* gs  = (float*)(sm + SM_G);
    float* bes = (float*)(sm + SM_BE);
    float2* part = (float2*)(sm + SM_PART);
    if (t < 128) { bs[t] = b[t]; gs[t] = g[t]; bes[t] = be[t]; }
    __syncthreads();

    int wrow = (warp & 1) * 32, wcol = (warp >> 1) * 32, cg = warp >> 1;
    int rbase = wrow + (lane >> 2);

    float s[4] = {0.f, 0.f, 0.f, 0.f}, q[4] = {0.f, 0.f, 0.f, 0.f};
#pragma unroll
    for (int rt = 0; rt < 2; rt++)
#pragma unroll
        for (int nt = 0; nt < 4; nt++) {
            int di = (rt * 4 + nt) * 4;
            int c0 = wcol + nt * 8 + (lane & 3) * 2;
            float x0 = d[di + 0] + bs[c0];
            float x1 = d[di + 1] + bs[c0 + 1];
            float x2 = d[di + 2] + bs[c0];
            float x3 = d[di + 3] + bs[c0 + 1];
            d[di + 0] = x0; d[di + 1] = x1; d[di + 2] = x2; d[di + 3] = x3;
            s[rt * 2]     += x0 + x1; q[rt * 2]     += x0 * x0 + x1 * x1;
            s[rt * 2 + 1] += x2 + x3; q[rt * 2 + 1] += x2 * x2 + x3 * x3;
        }
#pragma unroll
    for (int j = 0; j < 4; j++) {
        s[j] += __shfl_xor_sync(0xffffffffu, s[j], 1); s[j] += __shfl_xor_sync(0xffffffffu, s[j], 2);
        q[j] += __shfl_xor_sync(0xffffffffu, q[j], 1); q[j] += __shfl_xor_sync(0xffffffffu, q[j], 2);
    }
    if ((lane & 3) == 0) {
#pragma unroll
        for (int j = 0; j < 4; j++) {
            int row = rbase + (j & 1) * 8 + (j >> 1) * 16;
            part[row * 4 + cg] = make_float2(s[j], q[j]);
        }
    }
    __syncthreads();

    float m[4], rv[4];
#pragma unroll
    for (int j = 0; j < 4; j++) {
        int row = rbase + (j & 1) * 8 + (j >> 1) * 16;
        float2 p0 = part[row * 4 + 0], p1 = part[row * 4 + 1];
        float2 p2 = part[row * 4 + 2], p3 = part[row * 4 + 3];
        float sum = p0.x + p1.x + p2.x + p3.x;
        float qq  = p0.y + p1.y + p2.y + p3.y;
        m[j]  = sum * (1.f / 128.f);
        rv[j] = rsqrtf(qq * (1.f / 128.f) - m[j] * m[j] + EPSV);
    }

    float* stg = (float*)sm;
#pragma unroll
    for (int rt = 0; rt < 2; rt++)
#pragma unroll
        for (int nt = 0; nt < 4; nt++) {
            int di = (rt * 4 + nt) * 4;
            int c0 = wcol + nt * 8 + (lane & 3) * 2;
            int j0 = rt * 2, j1 = rt * 2 + 1;
            float y0 = fmaxf(fmaf((d[di + 0] - m[j0]) * rv[j0], gs[c0],     bes[c0]),     0.f);
            float y1 = fmaxf(fmaf((d[di + 1] - m[j0]) * rv[j0], gs[c0 + 1], bes[c0 + 1]), 0.f);
            float y2 = fmaxf(fmaf((d[di + 2] - m[j1]) * rv[j1], gs[c0],     bes[c0]),     0.f);
            float y3 = fmaxf(fmaf((d[di + 3] - m[j1]) * rv[j1], gs[c0 + 1], bes[c0 + 1]), 0.f);
            int r0 = rbase + rt * 16;
            int r1 = r0 + 8;
            if (mode == 0) {
                uint32_t h, l;
                uint32_t o0 = (uint32_t)(r0 * AS + dstcol + c0) * 2u;
                split2(y0, y1, h, l);
                *(uint32_t*)(sm + A_H + o0) = h;
                *(uint32_t*)(sm + A_L + o0) = l;
                uint32_t o1 = (uint32_t)(r1 * AS + dstcol + c0) * 2u;
                split2(y2, y3, h, l);
                *(uint32_t*)(sm + A_H + o1) = h;
                *(uint32_t*)(sm + A_L + o1) = l;
            } else {
                *(float2*)(stg + r0 * STG_STRIDE + c0) = make_float2(y0, y1);
                *(float2*)(stg + r1 * STG_STRIDE + c0) = make_float2(y2, y3);
            }
        }
}

// ---------------- edge kernel ----------------
__global__ __launch_bounds__(256, 2)
void edge_kernel(const float* __restrict__ h, const float* __restrict__ bond,
                 const int* __restrict__ src, const int* __restrict__ dst,
                 const unsigned char* __restrict__ wlev,
                 const float* __restrict__ b1, const float* __restrict__ g1, const float* __restrict__ be1,
                 const float* __restrict__ b2, const float* __restrict__ g2, const float* __restrict__ be2,
                 float* __restrict__ agg, int E) {
    extern __shared__ __align__(16) unsigned char sm[];
    uint32_t smb = smem_u32(sm);
    int t = threadIdx.x, lane = t & 31, warp = t >> 5;
    long long e0 = (long long)blockIdx.x * ROWS;
    int nvalid = (int)min((long long)ROWS, (long long)E - e0);

    int* ssm = (int*)(sm + SM_SRC);
    int* dsm = (int*)(sm + SM_DST);
    if (t < ROWS) {
        ssm[t] = (t < nvalid) ? src[e0 + t] : 0;
        dsm[t] = (t < nvalid) ? dst[e0 + t] : 0;
    }
    __syncthreads();

    gather64(sm, (const float4*)h, ssm, 0, 0, nvalid, t);
    gather64(sm, (const float4*)bond, nullptr, e0, 128, nvalid, t);

    float d[32];
    run_layer(sm, smb, wlev + OFF_BW1, 8, 0, d, t, lane, warp);
    epilogue(sm, d, b1, g1, be1, 0, 0, t, lane, warp);
    run_layer(sm, smb, wlev + OFF_BW2, 4, 0, d, t, lane, warp);
    epilogue(sm, d, b2, g2, be2, 1, 0, t, lane, warp);
    __syncthreads();

    const float* stg = (const float*)sm;
    int col = t & 127;
    for (int r = t >> 7; r < nvalid; r += 2)
        atomicAdd(&agg[(size_t)dsm[r] * 128 + col], stg[r * STG_STRIDE + col]);
}

// ---------------- node kernel ----------------
__global__ __launch_bounds__(256, 2)
void node_kernel(const float* __restrict__ ax, const float* __restrict__ aggin,
                 const unsigned char* __restrict__ wlev,
                 const float* __restrict__ sb1, const float* __restrict__ sg1, const float* __restrict__ sbe1,
                 const float* __restrict__ sb2, const float* __restrict__ sg2, const float* __restrict__ sbe2,
                 const float* __restrict__ hb, const float* __restrict__ hg, const float* __restrict__ hbe,
                 float* __restrict__ out, int N) {
    extern __shared__ __align__(16) unsigned char sm[];
    uint32_t smb = smem_u32(sm);
    int t = threadIdx.x, lane = t & 31, warp = t >> 5;
    long long n0 = (long long)blockIdx.x * ROWS;
    int nvalid = (int)min((long long)ROWS, (long long)N - n0);

    gather64(sm, (const float4*)ax, nullptr, n0, 0, nvalid, t);
    gather64(sm, (const float4*)aggin, nullptr, n0, 128, nvalid, t);

    float d[32];
    run_layer(sm, smb, wlev + OFF_SW1, 8, 0, d, t, lane, warp);
    epilogue(sm, d, sb1, sg1, sbe1, 0, 128, t, lane, warp);   // f1 -> cols 128..255 (keep ax)
    run_layer(sm, smb, wlev + OFF_SW2, 4, 128, d, t, lane, warp);
    epilogue(sm, d, sb2, sg2, sbe2, 0, 128, t, lane, warp);   // f2 -> cols 128..255
    run_layer(sm, smb, wlev + OFF_HW, 8, 0, d, t, lane, warp);
    epilogue(sm, d, hb, hg, hbe, 1, 0, t, lane, warp);
    __syncthreads();

    const float* stg = (const float*)sm;
    int col = t & 127;
    for (int r = t >> 7; r < nvalid; r += 2)
        out[(n0 + r) * 128 + col] = stg[r * STG_STRIDE + col];
}

// ---------------- weight prep: fp32 W[K][128] -> chunked W^T fp16 hi/lo ----------------
__global__ void prep_kernel(const float* __restrict__ bW1, const float* __restrict__ bW2,
                            const float* __restrict__ sW1, const float* __restrict__ sW2,
                            const float* __restrict__ hW) {
    int level = blockIdx.y, cid = blockIdx.x, t = threadIdx.x;
    const float* W; int c; uint32_t off; int K;
    if (cid < 8)       { W = bW1; c = cid;      off = OFF_BW1; K = 256; }
    else if (cid < 12) { W = bW2; c = cid - 8;  off = OFF_BW2; K = 128; }
    else if (cid < 20) { W = sW1; c = cid - 12; off = OFF_SW1; K = 256; }
    else if (cid < 24) { W = sW2; c = cid - 20; off = OFF_SW2; K = 128; }
    else               { W = hW;  c = cid - 24; off = OFF_HW;  K = 256; }

    const float* wsrc = W + (size_t)level * K * 128 + (size_t)c * 32 * 128;
    unsigned char* dstb = g_Wprep + (size_t)level * WLEVEL + off + (size_t)c * 16384u;
    for (int kk = 0; kk < 32; kk++) {
        float x = wsrc[kk * 128 + t];            // W[k][n], n = t
        __half hi = __float2half_rn(x);
        __half lo = __float2half_rn(x - __half2float(hi));
        uint32_t o = (uint32_t)(t * 32 + kk) * 2u;   // [n][k]
        *(__half*)(dstb + o)         = hi;
        *(__half*)(dstb + 8192u + o) = lo;
    }
}

// ---------------- kernel_launch ----------------
extern "C" void kernel_launch(void* const* d_in, const int* in_sizes, int n_in,
                              void* d_out, int out_size) {
    const float* subtree_h_top = (const float*)d_in[0];
    const float* atom_x_1      = (const float*)d_in[1];
    const float* atom_x_0      = (const float*)d_in[2];
    const float* bond_x_2      = (const float*)d_in[3];
    const float* bond_x_1      = (const float*)d_in[4];
    const float* branch_W1     = (const float*)d_in[5];
    const float* branch_b1     = (const float*)d_in[6];
    const float* branch_g1     = (const float*)d_in[7];
    const float* branch_beta1  = (const float*)d_in[8];
    const float* branch_W2     = (const float*)d_in[9];
    const float* branch_b2     = (const float*)d_in[10];
    const float* branch_g2     = (const float*)d_in[11];
    const float* branch_beta2  = (const float*)d_in[12];
    const float* sub_W1        = (const float*)d_in[13];
    const float* sub_b1        = (const float*)d_in[14];
    const float* sub_g1        = (const float*)d_in[15];
    const float* sub_beta1     = (const float*)d_in[16];
    const float* sub_W2        = (const float*)d_in[17];
    const float* sub_b2        = (const float*)d_in[18];
    const float* sub_g2        = (const float*)d_in[19];
    const float* sub_beta2     = (const float*)d_in[20];
    const float* head_W        = (const float*)d_in[21];
    const float* head_b        = (const float*)d_in[22];
    const float* head_g        = (const float*)d_in[23];
    const float* head_beta     = (const float*)d_in[24];
    const int*   src_2         = (const int*)d_in[25];
    const int*   dst_2         = (const int*)d_in[26];
    const int*   src_1         = (const int*)d_in[27];
    const int*   dst_1         = (const int*)d_in[28];

    const int n2 = in_sizes[0] / D;
    const int n1 = in_sizes[1] / D;
    const int n0 = in_sizes[2] / D;

    float* agg; cudaGetSymbolAddress((void**)&agg, g_agg);
    float* h1;  cudaGetSymbolAddress((void**)&h1,  g_h1);
    unsigned char* wprep; cudaGetSymbolAddress((void**)&wprep, g_Wprep);
    float* out = (float*)d_out;

    static bool attr_done = false;
    if (!attr_done) {
        cudaFuncSetAttribute(edge_kernel, cudaFuncAttributeMaxDynamicSharedMemorySize, SMEM_DYN);
        cudaFuncSetAttribute(node_kernel, cudaFuncAttributeMaxDynamicSharedMemorySize, SMEM_DYN);
        attr_done = true;
    }

    const int V = D;

    prep_kernel<<<dim3(32, 2), 128>>>(branch_W1, branch_W2, sub_W1, sub_W2, head_W);

    // level 0: n2 edges -> n1 nodes
    cudaMemsetAsync(agg, 0, (size_t)n1 * D * sizeof(float));
    edge_kernel<<<(n2 + ROWS - 1) / ROWS, 256, SMEM_DYN>>>(
        subtree_h_top, bond_x_2, src_2, dst_2, wprep,
        branch_b1, branch_g1, branch_beta1,
        branch_b2, branch_g2, branch_beta2, agg, n2);
    node_kernel<<<(n1 + ROWS - 1) / ROWS, 256, SMEM_DYN>>>(
        atom_x_1, agg, wprep,
        sub_b1, sub_g1, sub_beta1,
        sub_b2, sub_g2, sub_beta2,
        head_b, head_g, head_beta, h1, n1);

    // level 1: n1 edges -> n0 nodes
    cudaMemsetAsync(agg, 0, (size_t)n0 * D * sizeof(float));
    edge_kernel<<<(n1 + ROWS - 1) / ROWS, 256, SMEM_DYN>>>(
        h1, bond_x_1, src_1, dst_1, wprep + WLEVEL,
        branch_b1 + V, branch_g1 + V, branch_beta1 + V,
        branch_b2 + V, branch_g2 + V, branch_beta2 + V, agg, n1);
    node_kernel<<<(n0 + ROWS - 1) / ROWS, 256, SMEM_DYN>>>(
        atom_x_0, agg, wprep + WLEVEL,
        sub_b1 + V, sub_g1 + V, sub_beta1 + V,
        sub_b2 + V, sub_g2 + V, sub_beta2 + V,
        head_b + V, head_g + V, head_beta + V, out, n0);
}